// round 6
// baseline (speedup 1.0000x reference)
#include <cuda_runtime.h>
#include <cuda_bf16.h>
#include <cstdint>

#define N_NODES  50000
#define N_EDGES  400000
#define N_GRAPHS 64
#define LDT 40               // padded smem row: 40 bf16 = 80 B (conflict-free, 16B mult)

// ============================ device scratch ===============================
__device__ __nv_bfloat16 g_xhi[N_NODES * 512];   // x pre-split
__device__ __nv_bfloat16 g_xlo[N_NODES * 512];
__device__ __nv_bfloat16 g_w1hi[256 * 512];      // [W1l|W1r]^T hi  [256 n][512 k]
__device__ __nv_bfloat16 g_w1lo[256 * 512];
__device__ __nv_bfloat16 g_w2hi[64 * 128];       // [W2l|W2r]^T hi  [64 n][128 k]
__device__ __nv_bfloat16 g_w2lo[64 * 128];
__device__ __nv_bfloat16 g_h1hi[N_NODES * 128];  // h1 pre-split
__device__ __nv_bfloat16 g_h1lo[N_NODES * 128];
__device__ float g_y1[N_NODES * 256];
__device__ float g_agg1[N_NODES * 128];
__device__ float g_cnt[N_NODES];
__device__ float g_y2[N_NODES * 64];
__device__ float g_agg2[N_NODES * 32];
__device__ float g_gsum[N_GRAPHS * 32];
__device__ float g_gcnt[N_GRAPHS];

// ============================ zero accumulators ============================
__global__ void zero_kernel() {
    size_t i = (size_t)blockIdx.x * blockDim.x + threadIdx.x;
    size_t stride = (size_t)gridDim.x * blockDim.x;
    for (size_t k = i; k < (size_t)N_NODES * 128; k += stride) g_agg1[k] = 0.f;
    for (size_t k = i; k < (size_t)N_NODES * 32;  k += stride) g_agg2[k] = 0.f;
    for (size_t k = i; k < (size_t)N_NODES;       k += stride) g_cnt[k]  = 0.f;
    for (size_t k = i; k < (size_t)N_GRAPHS * 32; k += stride) g_gsum[k] = 0.f;
    for (size_t k = i; k < (size_t)N_GRAPHS;      k += stride) g_gcnt[k] = 0.f;
}

// ============================ helpers ======================================
__device__ __forceinline__ uint32_t su32(const void* p) {
    return (uint32_t)__cvta_generic_to_shared(p);
}
__device__ __forceinline__ uint32_t pack_bf2(__nv_bfloat16 a, __nv_bfloat16 b) {
    __nv_bfloat162 t = __halves2bfloat162(a, b);
    return *(uint32_t*)&t;
}
__device__ __forceinline__ void split4(float4 v, uint2& h, uint2& l) {
    __nv_bfloat16 h0 = __float2bfloat16_rn(v.x), h1 = __float2bfloat16_rn(v.y);
    __nv_bfloat16 h2 = __float2bfloat16_rn(v.z), h3 = __float2bfloat16_rn(v.w);
    h = make_uint2(pack_bf2(h0, h1), pack_bf2(h2, h3));
    l = make_uint2(pack_bf2(__float2bfloat16_rn(v.x - __bfloat162float(h0)),
                            __float2bfloat16_rn(v.y - __bfloat162float(h1))),
                   pack_bf2(__float2bfloat16_rn(v.z - __bfloat162float(h2)),
                            __float2bfloat16_rn(v.w - __bfloat162float(h3))));
}
__device__ __forceinline__ void mma16816(float* c, const uint32_t* a, const uint32_t* b) {
    asm volatile(
        "mma.sync.aligned.m16n8k16.row.col.f32.bf16.bf16.f32 "
        "{%0,%1,%2,%3}, {%4,%5,%6,%7}, {%8,%9}, {%0,%1,%2,%3};"
        : "+f"(c[0]), "+f"(c[1]), "+f"(c[2]), "+f"(c[3])
        : "r"(a[0]), "r"(a[1]), "r"(a[2]), "r"(a[3]), "r"(b[0]), "r"(b[1]));
}
__device__ __forceinline__ void ldsm4(uint32_t* r, uint32_t addr) {
    asm volatile("ldmatrix.sync.aligned.m8n8.x4.shared.b16 {%0,%1,%2,%3}, [%4];"
                 : "=r"(r[0]), "=r"(r[1]), "=r"(r[2]), "=r"(r[3]) : "r"(addr));
}
__device__ __forceinline__ void cp16(uint32_t saddr, const void* gaddr, uint32_t sz) {
    asm volatile("cp.async.cg.shared.global [%0], [%1], 16, %2;"
                 :: "r"(saddr), "l"(gaddr), "r"(sz) : "memory");
}

// ==================== conversions (pre-split to bf16 hi/lo) ================
__global__ void convert_x(const float4* __restrict__ x4) {
    size_t total = (size_t)N_NODES * 64;   // groups of 8 floats
    for (size_t i = (size_t)blockIdx.x * blockDim.x + threadIdx.x; i < total;
         i += (size_t)gridDim.x * blockDim.x) {
        float4 a = x4[2 * i], b = x4[2 * i + 1];
        uint2 h0, l0, h1, l1;
        split4(a, h0, l0);
        split4(b, h1, l1);
        ((uint4*)g_xhi)[i] = make_uint4(h0.x, h0.y, h1.x, h1.y);
        ((uint4*)g_xlo)[i] = make_uint4(l0.x, l0.y, l1.x, l1.y);
    }
}
__global__ void convert_w(const float* __restrict__ Wl, const float* __restrict__ Wr) {
    int idx = blockIdx.x * blockDim.x + threadIdx.x;
    if (idx >= 256 * 512) return;
    int n = idx >> 9, k = idx & 511;
    float v = (n < 128) ? Wl[k * 128 + n] : Wr[k * 128 + (n - 128)];
    __nv_bfloat16 h = __float2bfloat16_rn(v);
    g_w1hi[idx] = h;
    g_w1lo[idx] = __float2bfloat16_rn(v - __bfloat162float(h));
}
__global__ void convert_w2(const float* __restrict__ Wl, const float* __restrict__ Wr) {
    int idx = blockIdx.x * blockDim.x + threadIdx.x;
    if (idx >= 64 * 128) return;
    int n = idx >> 7, k = idx & 127;
    float v = (n < 32) ? Wl[k * 32 + n] : Wr[k * 32 + (n - 32)];
    __nv_bfloat16 h = __float2bfloat16_rn(v);
    g_w2hi[idx] = h;
    g_w2lo[idx] = __float2bfloat16_rn(v - __bfloat162float(h));
}

// ===== GEMM1: y1[M,256] = x[M,512] @ W1^T (bf16x3, cp.async 2-stage) =======
// 512 threads, CTA tile 128(M) x 256(N), warp tile 32x64, BK=32.
// smem per stage: Ahi(10240) Alo(10240) Bhi(20480) Blo(20480) = 61440 B.
#define SSTRIDE 61440
#define SM_G1   (2 * SSTRIDE)

__global__ __launch_bounds__(512) void gemm1_mma(float* __restrict__ y1, int M) {
    extern __shared__ char smem[];
    const uint32_t sb = su32(smem);
    const int tid  = threadIdx.x;
    const int lane = tid & 31, wid = tid >> 5;
    const int wm = (wid & 3) * 32;
    const int wn = (wid >> 2) * 64;
    const int rowBase = blockIdx.x * 128;

    float acc[2][8][4];
#pragma unroll
    for (int i = 0; i < 2; i++)
#pragma unroll
        for (int j = 0; j < 8; j++)
#pragma unroll
            for (int q = 0; q < 4; q++) acc[i][j][q] = 0.f;

    const int g4 = lane & 3, gID = lane >> 2;
    const int sel = lane >> 3;
    const uint32_t rowInSel = (uint32_t)((sel & 1) * 8 + (lane & 7));
    const uint32_t colSel = (uint32_t)((sel >> 1) * 16);
    const uint32_t aOff = (wm + rowInSel) * 80 + colSel;
    const uint32_t bOff = (wn + rowInSel) * 80 + colSel;

    // load mappings
    const int arow = tid >> 2, aq = tid & 3;            // A: 512 chunks of 16B
    const int gr = rowBase + arow;
    const uint32_t asz = (gr < M) ? 16u : 0u;
    const size_t agi = (size_t)((gr < M) ? gr : 0) * 512 + aq * 8;
    const int brow0 = tid >> 2, bq0 = tid & 3;          // B: 1024 chunks, 2/thread
    const int brow1 = (tid + 512) >> 2, bq1 = (tid + 512) & 3;

    auto issue = [&](int kt, int s) {
        uint32_t st = sb + s * SSTRIDE;
        cp16(st + arow * 80 + aq * 16,           g_xhi + agi + kt, asz);
        cp16(st + 10240 + arow * 80 + aq * 16,   g_xlo + agi + kt, asz);
        cp16(st + 20480 + brow0 * 80 + bq0 * 16, g_w1hi + (size_t)brow0 * 512 + kt + bq0 * 8, 16);
        cp16(st + 20480 + brow1 * 80 + bq1 * 16, g_w1hi + (size_t)brow1 * 512 + kt + bq1 * 8, 16);
        cp16(st + 40960 + brow0 * 80 + bq0 * 16, g_w1lo + (size_t)brow0 * 512 + kt + bq0 * 8, 16);
        cp16(st + 40960 + brow1 * 80 + bq1 * 16, g_w1lo + (size_t)brow1 * 512 + kt + bq1 * 8, 16);
        asm volatile("cp.async.commit_group;" ::: "memory");
    };

    issue(0, 0);
    for (int it = 0; it < 16; it++) {
        const int s = it & 1;
        if (it + 1 < 16) {
            issue((it + 1) * 32, s ^ 1);
            asm volatile("cp.async.wait_group 1;" ::: "memory");
        } else {
            asm volatile("cp.async.wait_group 0;" ::: "memory");
        }
        __syncthreads();

        const uint32_t stage = sb + s * SSTRIDE;
#pragma unroll
        for (int cmb = 0; cmb < 3; cmb++) {
            const uint32_t Ab = stage + (cmb == 2 ? 10240u : 0u);
            const uint32_t Bb = stage + 20480u + (cmb == 1 ? 20480u : 0u);
#pragma unroll
            for (int kk2 = 0; kk2 < 2; kk2++) {
                uint32_t a[2][4];
                ldsm4(a[0], Ab + aOff + kk2 * 32);
                ldsm4(a[1], Ab + aOff + 1280 + kk2 * 32);
#pragma unroll
                for (int ntp = 0; ntp < 4; ntp++) {
                    uint32_t b[4];
                    ldsm4(b, Bb + bOff + ntp * 1280 + kk2 * 32);
                    uint32_t b0[2] = {b[0], b[2]};
                    uint32_t b1[2] = {b[1], b[3]};
                    mma16816(acc[0][2 * ntp],     a[0], b0);
                    mma16816(acc[1][2 * ntp],     a[1], b0);
                    mma16816(acc[0][2 * ntp + 1], a[0], b1);
                    mma16816(acc[1][2 * ntp + 1], a[1], b1);
                }
            }
        }
        __syncthreads();
    }

#pragma unroll
    for (int mt = 0; mt < 2; mt++) {
        int r0 = rowBase + wm + mt * 16 + gID;
#pragma unroll
        for (int nt = 0; nt < 8; nt++) {
            int cc = wn + nt * 8 + g4 * 2;
            if (r0 < M)
                *(float2*)(y1 + (size_t)r0 * 256 + cc) = make_float2(acc[mt][nt][0], acc[mt][nt][1]);
            if (r0 + 8 < M)
                *(float2*)(y1 + (size_t)(r0 + 8) * 256 + cc) = make_float2(acc[mt][nt][2], acc[mt][nt][3]);
        }
    }
}

// ============ GEMM2: y2[M,64] = h1[M,128] @ W2^T (bf16x3, presplit) =========
__global__ __launch_bounds__(256) void gemm2_mma(float* __restrict__ y2, int M) {
    __shared__ __nv_bfloat16 sAhi[128][LDT], sAlo[128][LDT];
    __shared__ __nv_bfloat16 sBhi[64][LDT],  sBlo[64][LDT];

    const int tid  = threadIdx.x;
    const int lane = tid & 31, wid = tid >> 5;
    const int wm = (wid & 3) * 32;
    const int wn = (wid >> 2) * 32;
    const int rowBase = blockIdx.x * 128;

    float acc[2][4][4];
#pragma unroll
    for (int i = 0; i < 2; i++)
#pragma unroll
        for (int j = 0; j < 4; j++)
#pragma unroll
            for (int q = 0; q < 4; q++) acc[i][j][q] = 0.f;

    const int g4 = lane & 3, gID = lane >> 2;
    const int sel = lane >> 3;
    const uint32_t rowInSel = (uint32_t)((sel & 1) * 8 + (lane & 7));
    const uint32_t colSel = (uint32_t)((sel >> 1) * 16);

    const uint32_t aHiB = su32(sAhi), aLoB = su32(sAlo);
    const uint32_t bHiB = su32(sBhi), bLoB = su32(sBlo);
    const uint32_t aOff = (wm + rowInSel) * (LDT * 2) + colSel;
    const uint32_t bOff = (wn + rowInSel) * (LDT * 2) + colSel;

    for (int kt = 0; kt < 128; kt += 32) {
#pragma unroll
        for (int p = 0; p < 2; p++) {
            int j = tid + p * 256;
            int row = j >> 2, q = j & 3;
            int gr = rowBase + row;
            uint4 vh = make_uint4(0, 0, 0, 0), vl = vh;
            if (gr < M) {
                size_t gi = (size_t)gr * 128 + kt + q * 8;
                vh = *(const uint4*)(g_h1hi + gi);
                vl = *(const uint4*)(g_h1lo + gi);
            }
            *(uint4*)&sAhi[row][q * 8] = vh;
            *(uint4*)&sAlo[row][q * 8] = vl;
        }
        {
            int row = tid >> 2, q = tid & 3;
            size_t gi = (size_t)row * 128 + kt + q * 8;
            *(uint4*)&sBhi[row][q * 8] = *(const uint4*)(g_w2hi + gi);
            *(uint4*)&sBlo[row][q * 8] = *(const uint4*)(g_w2lo + gi);
        }
        __syncthreads();

#pragma unroll
        for (int cmb = 0; cmb < 3; cmb++) {
            uint32_t Ab = (cmb == 2) ? aLoB : aHiB;
            uint32_t Bb = (cmb == 1) ? bLoB : bHiB;
#pragma unroll
            for (int kk2 = 0; kk2 < 2; kk2++) {
                uint32_t a[2][4];
                ldsm4(a[0], Ab + aOff + kk2 * 32);
                ldsm4(a[1], Ab + aOff + 1280 + kk2 * 32);
#pragma unroll
                for (int ntp = 0; ntp < 2; ntp++) {
                    uint32_t b[4];
                    ldsm4(b, Bb + bOff + ntp * 1280 + kk2 * 32);
                    uint32_t b0[2] = {b[0], b[2]};
                    uint32_t b1[2] = {b[1], b[3]};
                    mma16816(acc[0][2 * ntp],     a[0], b0);
                    mma16816(acc[1][2 * ntp],     a[1], b0);
                    mma16816(acc[0][2 * ntp + 1], a[0], b1);
                    mma16816(acc[1][2 * ntp + 1], a[1], b1);
                }
            }
        }
        __syncthreads();
    }

#pragma unroll
    for (int mt = 0; mt < 2; mt++) {
        int r0 = rowBase + wm + mt * 16 + gID;
#pragma unroll
        for (int nt = 0; nt < 4; nt++) {
            int cc = wn + nt * 8 + g4 * 2;
            if (r0 < M)
                *(float2*)(y2 + (size_t)r0 * 64 + cc) = make_float2(acc[mt][nt][0], acc[mt][nt][1]);
            if (r0 + 8 < M)
                *(float2*)(y2 + (size_t)(r0 + 8) * 64 + cc) = make_float2(acc[mt][nt][2], acc[mt][nt][3]);
        }
    }
}

// ---------------- edge aggregation, layer 1 (128 feats, warp per edge) -----
__global__ void edge_agg1(const int* __restrict__ ei) {
    int gtid = blockIdx.x * blockDim.x + threadIdx.x;
    int e = gtid >> 5;
    int lane = gtid & 31;
    if (e >= N_EDGES) return;
    int src = ei[e];
    int dst = ei[N_EDGES + e];
    float4 v = *(const float4*)(g_y1 + (size_t)src * 256 + lane * 4);
    float* p = g_agg1 + (size_t)dst * 128 + lane * 4;
    asm volatile("red.global.add.v4.f32 [%0], {%1,%2,%3,%4};"
                 :: "l"(p), "f"(v.x), "f"(v.y), "f"(v.z), "f"(v.w) : "memory");
    if (lane == 0) atomicAdd(&g_cnt[dst], 1.0f);
}

// ------- layer-1 epilogue: h1 = relu(agg/cnt + b1l + y1r), split hi/lo -----
__global__ void epi1(const float* __restrict__ b1l) {
    int idx = blockIdx.x * blockDim.x + threadIdx.x;   // N_NODES*32 float4 groups
    if (idx >= N_NODES * 32) return;
    int m = idx >> 5, q = idx & 31;
    float inv = 1.0f / fmaxf(g_cnt[m], 1.0f);
    float4 a = ((const float4*)g_agg1)[idx];
    float4 r = ((const float4*)g_y1)[(size_t)m * 64 + 32 + q];
    float4 b = ((const float4*)b1l)[q];
    float4 o;
    o.x = fmaxf(a.x * inv + b.x + r.x, 0.f);
    o.y = fmaxf(a.y * inv + b.y + r.y, 0.f);
    o.z = fmaxf(a.z * inv + b.z + r.z, 0.f);
    o.w = fmaxf(a.w * inv + b.w + r.w, 0.f);
    uint2 h, l;
    split4(o, h, l);
    ((uint2*)g_h1hi)[idx] = h;
    ((uint2*)g_h1lo)[idx] = l;
}

// ---------------- edge aggregation, layer 2 (32 feats, 8 threads/edge) -----
__global__ void edge_agg2(const int* __restrict__ ei) {
    int gtid = blockIdx.x * blockDim.x + threadIdx.x;
    int e = gtid >> 3;
    int lane = gtid & 7;
    if (e >= N_EDGES) return;
    int src = ei[e];
    int dst = ei[N_EDGES + e];
    float4 v = *(const float4*)(g_y2 + (size_t)src * 64 + lane * 4);
    float* p = g_agg2 + (size_t)dst * 32 + lane * 4;
    asm volatile("red.global.add.v4.f32 [%0], {%1,%2,%3,%4};"
                 :: "l"(p), "f"(v.x), "f"(v.y), "f"(v.z), "f"(v.w) : "memory");
}

// ---------------- fused layer-2 epilogue + per-graph mean pool --------------
__global__ void pool_kernel(const int* __restrict__ batch, const float* __restrict__ b2l) {
    int f = threadIdx.x;           // 32
    int yid = threadIdx.y;         // 8
    int n0 = blockIdx.x * 512 + yid;
    float b = b2l[f];
    float acc = 0.f, cacc = 0.f;
    int cur = -1;
    for (int it = 0; it < 64; it++) {
        int n = n0 + it * 8;
        if (n < N_NODES) {
            int g = batch[n];
            if (g != cur) {
                if (cur >= 0) {
                    atomicAdd(&g_gsum[cur * 32 + f], acc);
                    if (f == 0) atomicAdd(&g_gcnt[cur], cacc);
                }
                cur = g; acc = 0.f; cacc = 0.f;
            }
            float inv = 1.0f / fmaxf(g_cnt[n], 1.0f);
            float v = g_agg2[(size_t)n * 32 + f] * inv + b + g_y2[(size_t)n * 64 + 32 + f];
            acc += fmaxf(v, 0.f);
            cacc += 1.f;
        }
    }
    if (cur >= 0) {
        atomicAdd(&g_gsum[cur * 32 + f], acc);
        if (f == 0) atomicAdd(&g_gcnt[cur], cacc);
    }
}

// ---------------- final tiny MLP (encoder head + decoder) ------------------
__global__ void mlp_kernel(const float* __restrict__ Wl1, const float* __restrict__ bl1,
                           const float* __restrict__ Wl2, const float* __restrict__ bl2,
                           const float* __restrict__ Wd1, const float* __restrict__ bd1,
                           const float* __restrict__ Wd2, const float* __restrict__ bd2,
                           const float* __restrict__ Wd3, const float* __restrict__ bd3,
                           float* __restrict__ out) {
    __shared__ float sWl1[1024], sWl2[512], sWd1[512], sWd2[1024], sWd3[1600];
    __shared__ float sbl1[32], sbl2[16], sbd1[32], sbd2[32], sbd3[50];
    int t = threadIdx.x;           // 64
    for (int i = t; i < 1024; i += 64) sWl1[i] = Wl1[i];
    for (int i = t; i < 512;  i += 64) sWl2[i] = Wl2[i];
    for (int i = t; i < 512;  i += 64) sWd1[i] = Wd1[i];
    for (int i = t; i < 1024; i += 64) sWd2[i] = Wd2[i];
    for (int i = t; i < 1600; i += 64) sWd3[i] = Wd3[i];
    if (t < 32) sbl1[t] = bl1[t];
    if (t < 16) sbl2[t] = bl2[t];
    if (t < 32) sbd1[t] = bd1[t];
    if (t < 32) sbd2[t] = bd2[t];
    for (int i = t; i < 50; i += 64) sbd3[i] = bd3[i];
    __syncthreads();
    if (t >= N_GRAPHS) return;

    float gv[32];
    float inv = 1.0f / fmaxf(g_gcnt[t], 1.0f);
#pragma unroll
    for (int i = 0; i < 32; i++) gv[i] = g_gsum[t * 32 + i] * inv;

    float a[32];
#pragma unroll
    for (int j = 0; j < 32; j++) {
        float s = sbl1[j];
#pragma unroll
        for (int i = 0; i < 32; i++) s = fmaf(gv[i], sWl1[i * 32 + j], s);
        a[j] = fmaxf(s, 0.f);
    }
    float enc[16];
#pragma unroll
    for (int j = 0; j < 16; j++) {
        float s = sbl2[j];
#pragma unroll
        for (int i = 0; i < 32; i++) s = fmaf(a[i], sWl2[i * 16 + j], s);
        enc[j] = s > 0.f ? s : 0.1f * s;
    }
#pragma unroll
    for (int j = 0; j < 16; j++) out[t * 16 + j] = enc[j];

    float z1[32];
#pragma unroll
    for (int j = 0; j < 32; j++) {
        float s = sbd1[j];
#pragma unroll
        for (int i = 0; i < 16; i++) s = fmaf(enc[i], sWd1[i * 32 + j], s);
        z1[j] = s > 0.f ? s : 0.1f * s;
    }
    float z2[32];
#pragma unroll
    for (int j = 0; j < 32; j++) {
        float s = sbd2[j];
#pragma unroll
        for (int i = 0; i < 32; i++) s = fmaf(z1[i], sWd2[i * 32 + j], s);
        z2[j] = s > 0.f ? s : 0.1f * s;
    }
#pragma unroll
    for (int j = 0; j < 50; j++) {
        float s = sbd3[j];
#pragma unroll
        for (int i = 0; i < 32; i++) s = fmaf(z2[i], sWd3[i * 50 + j], s);
        out[1024 + t * 50 + j] = s;
    }
}

// ---------------- launch ----------------------------------------------------
extern "C" void kernel_launch(void* const* d_in, const int* in_sizes, int n_in,
                              void* d_out, int out_size) {
    const float* x   = (const float*)d_in[0];
    const int*   ei  = (const int*)d_in[1];
    const int*   bat = (const int*)d_in[2];
    const float* W1l = (const float*)d_in[3];
    const float* b1l = (const float*)d_in[4];
    const float* W1r = (const float*)d_in[5];
    const float* W2l = (const float*)d_in[6];
    const float* b2l = (const float*)d_in[7];
    const float* W2r = (const float*)d_in[8];
    const float* Wl1 = (const float*)d_in[9];
    const float* bl1 = (const float*)d_in[10];
    const float* Wl2 = (const float*)d_in[11];
    const float* bl2 = (const float*)d_in[12];
    const float* Wd1 = (const float*)d_in[13];
    const float* bd1 = (const float*)d_in[14];
    const float* Wd2 = (const float*)d_in[15];
    const float* bd2 = (const float*)d_in[16];
    const float* Wd3 = (const float*)d_in[17];
    const float* bd3 = (const float*)d_in[18];
    float* out = (float*)d_out;

    float *p_y1, *p_y2;
    cudaGetSymbolAddress((void**)&p_y1, g_y1);
    cudaGetSymbolAddress((void**)&p_y2, g_y2);

    cudaFuncSetAttribute(gemm1_mma, cudaFuncAttributeMaxDynamicSharedMemorySize, SM_G1);

    zero_kernel<<<1184, 256>>>();
    convert_w<<<512, 256>>>(W1l, W1r);
    convert_w2<<<32, 256>>>(W2l, W2r);
    convert_x<<<12500, 256>>>((const float4*)x);

    // GEMM1 (tensor pipe, cp.async double-buffered): M=50000, K=512, N=256
    gemm1_mma<<<(N_NODES + 127) / 128, 512, SM_G1>>>(p_y1, N_NODES);

    edge_agg1<<<50000, 256>>>(ei);
    epi1<<<(N_NODES * 32 + 255) / 256, 256>>>(b1l);

    // GEMM2 (tensor pipe): M=50000, K=128, N=64
    gemm2_mma<<<(N_NODES + 127) / 128, 256>>>(p_y2, N_NODES);

    edge_agg2<<<12500, 256>>>(ei);

    {
        dim3 blk(32, 8);
        pool_kernel<<<(N_NODES + 511) / 512, blk>>>(bat, b2l);
    }

    mlp_kernel<<<1, 64>>>(Wl1, bl1, Wl2, bl2, Wd1, bd1, Wd2, bd2, Wd3, bd3, out);
}

// round 7
// speedup vs baseline: 1.0734x; 1.0734x over previous
#include <cuda_runtime.h>
#include <cuda_fp16.h>
#include <cstdint>

#define N_NODES  50000
#define N_EDGES  400000
#define N_GRAPHS 64

// ============================ device scratch ===============================
__device__ __half g_xh[N_NODES * 512];     // x hi (fp16)
__device__ __half g_xl[N_NODES * 512];     // x lo (fp16)
__device__ __half g_w1[256 * 512];         // [W1l|W1r]^T fp16  [256 n][512 k]
__device__ __half g_w2[64 * 128];          // [W2l|W2r]^T fp16  [64 n][128 k]
__device__ __half g_h1h[N_NODES * 128];    // h1 hi
__device__ __half g_h1l[N_NODES * 128];    // h1 lo
__device__ float g_y1[N_NODES * 256];
__device__ float g_agg1[N_NODES * 128];
__device__ float g_cnt[N_NODES];
__device__ float g_y2[N_NODES * 64];
__device__ float g_agg2[N_NODES * 32];
__device__ float g_gsum[N_GRAPHS * 32];
__device__ float g_gcnt[N_GRAPHS];

// ============================ zero accumulators ============================
__global__ void zero_kernel() {
    size_t i = (size_t)blockIdx.x * blockDim.x + threadIdx.x;
    size_t stride = (size_t)gridDim.x * blockDim.x;
    for (size_t k = i; k < (size_t)N_NODES * 128; k += stride) g_agg1[k] = 0.f;
    for (size_t k = i; k < (size_t)N_NODES * 32;  k += stride) g_agg2[k] = 0.f;
    for (size_t k = i; k < (size_t)N_NODES;       k += stride) g_cnt[k]  = 0.f;
    for (size_t k = i; k < (size_t)N_GRAPHS * 32; k += stride) g_gsum[k] = 0.f;
    for (size_t k = i; k < (size_t)N_GRAPHS;      k += stride) g_gcnt[k] = 0.f;
}

// ============================ helpers ======================================
__device__ __forceinline__ uint32_t su32(const void* p) {
    return (uint32_t)__cvta_generic_to_shared(p);
}
__device__ __forceinline__ uint32_t pack_h2(__half a, __half b) {
    __half2 t = __halves2half2(a, b);
    return *(uint32_t*)&t;
}
__device__ __forceinline__ void split4h(float4 v, uint2& h, uint2& l) {
    __half h0 = __float2half_rn(v.x), h1 = __float2half_rn(v.y);
    __half h2 = __float2half_rn(v.z), h3 = __float2half_rn(v.w);
    h = make_uint2(pack_h2(h0, h1), pack_h2(h2, h3));
    l = make_uint2(pack_h2(__float2half_rn(v.x - __half2float(h0)),
                           __float2half_rn(v.y - __half2float(h1))),
                   pack_h2(__float2half_rn(v.z - __half2float(h2)),
                           __float2half_rn(v.w - __half2float(h3))));
}
__device__ __forceinline__ void mma16816h(float* c, const uint32_t* a, const uint32_t* b) {
    asm volatile(
        "mma.sync.aligned.m16n8k16.row.col.f32.f16.f16.f32 "
        "{%0,%1,%2,%3}, {%4,%5,%6,%7}, {%8,%9}, {%0,%1,%2,%3};"
        : "+f"(c[0]), "+f"(c[1]), "+f"(c[2]), "+f"(c[3])
        : "r"(a[0]), "r"(a[1]), "r"(a[2]), "r"(a[3]), "r"(b[0]), "r"(b[1]));
}
__device__ __forceinline__ void ldsm4(uint32_t* r, uint32_t addr) {
    asm volatile("ldmatrix.sync.aligned.m8n8.x4.shared.b16 {%0,%1,%2,%3}, [%4];"
                 : "=r"(r[0]), "=r"(r[1]), "=r"(r[2]), "=r"(r[3]) : "r"(addr));
}

// ==================== conversions (fp16) ====================================
__global__ void convert_x(const float4* __restrict__ x4) {
    size_t total = (size_t)N_NODES * 64;   // groups of 8 floats
    for (size_t i = (size_t)blockIdx.x * blockDim.x + threadIdx.x; i < total;
         i += (size_t)gridDim.x * blockDim.x) {
        float4 a = x4[2 * i], b = x4[2 * i + 1];
        uint2 h0, l0, h1, l1;
        split4h(a, h0, l0);
        split4h(b, h1, l1);
        ((uint4*)g_xh)[i] = make_uint4(h0.x, h0.y, h1.x, h1.y);
        ((uint4*)g_xl)[i] = make_uint4(l0.x, l0.y, l1.x, l1.y);
    }
}
__global__ void convert_w(const float* __restrict__ Wl, const float* __restrict__ Wr) {
    int idx = blockIdx.x * blockDim.x + threadIdx.x;
    if (idx >= 256 * 512) return;
    int n = idx >> 9, k = idx & 511;
    float v = (n < 128) ? Wl[k * 128 + n] : Wr[k * 128 + (n - 128)];
    g_w1[idx] = __float2half_rn(v);
}
__global__ void convert_w2(const float* __restrict__ Wl, const float* __restrict__ Wr) {
    int idx = blockIdx.x * blockDim.x + threadIdx.x;
    if (idx >= 64 * 128) return;
    int n = idx >> 7, k = idx & 127;
    float v = (n < 32) ? Wl[k * 32 + n] : Wr[k * 32 + (n - 32)];
    g_w2[idx] = __float2half_rn(v);
}

// ===== GEMM1: y1[M,256] = x[M,512] @ W1^T  (fp16 x-split, 2 passes) ========
// 512 threads, CTA tile 128(M) x 256(N), BK=32, LDG->reg->STS double buffer.
// stage: Ah 128*80 + Al 128*80 + B 256*80 = 40960 B; 2 stages = 81920 B.
#define G1_STAGE 40960
#define SM_G1 (2 * G1_STAGE)

__global__ __launch_bounds__(512) void gemm1_mma(float* __restrict__ y1, int M) {
    extern __shared__ char smem[];
    const uint32_t sb = su32(smem);
    const int tid  = threadIdx.x;
    const int lane = tid & 31, wid = tid >> 5;
    const int wm = (wid & 3) * 32;
    const int wn = (wid >> 2) * 64;
    const int rowBase = blockIdx.x * 128;

    float acc[2][8][4];
#pragma unroll
    for (int i = 0; i < 2; i++)
#pragma unroll
        for (int j = 0; j < 8; j++)
#pragma unroll
            for (int q = 0; q < 4; q++) acc[i][j][q] = 0.f;

    const int g4 = lane & 3, gID = lane >> 2;
    const int sel = lane >> 3;
    const uint32_t rowInSel = (uint32_t)((sel & 1) * 8 + (lane & 7));
    const uint32_t colSel = (uint32_t)((sel >> 1) * 16);
    const uint32_t aOff = (wm + rowInSel) * 80 + colSel;
    const uint32_t bOff = (wn + rowInSel) * 80 + colSel;

    // load mappings
    const int arow = tid >> 2, aq = tid & 3;      // A: 512 16B-chunks (hi & lo)
    const int gra = rowBase + arow;
    const bool av = (gra < M);
    const size_t agi = (size_t)(av ? gra : 0) * 512 + aq * 8;
    const size_t bgi0 = (size_t)(tid >> 2) * 512 + (tid & 3) * 8;          // B rows 0..127
    const size_t bgi1 = (size_t)((tid >> 2) + 128) * 512 + (tid & 3) * 8;  // B rows 128..255
    const uint32_t sAh = arow * 80 + aq * 16;
    const uint32_t sBo0 = 20480 + (tid >> 2) * 80 + (tid & 3) * 16;
    const uint32_t sBo1 = 20480 + ((tid >> 2) + 128) * 80 + (tid & 3) * 16;

    uint4 rah, ral, rb0, rb1;
    const uint4 z4 = make_uint4(0, 0, 0, 0);

    auto loadRegs = [&](int kt) {
        rah = av ? *(const uint4*)(g_xh + agi + kt) : z4;
        ral = av ? *(const uint4*)(g_xl + agi + kt) : z4;
        rb0 = *(const uint4*)(g_w1 + bgi0 + kt);
        rb1 = *(const uint4*)(g_w1 + bgi1 + kt);
    };
    auto storeStage = [&](int s) {
        char* st = smem + s * G1_STAGE;
        *(uint4*)(st + sAh)         = rah;
        *(uint4*)(st + 10240 + sAh) = ral;
        *(uint4*)(st + sBo0)        = rb0;
        *(uint4*)(st + sBo1)        = rb1;
    };

    loadRegs(0);
    storeStage(0);
    __syncthreads();

    for (int it = 0; it < 16; it++) {
        const int s = it & 1;
        if (it < 15) loadRegs((it + 1) * 32);

        const uint32_t stage = sb + s * G1_STAGE;
#pragma unroll
        for (int pass = 0; pass < 2; pass++) {
            const uint32_t Ab = stage + (pass ? 10240u : 0u);
            const uint32_t Bb = stage + 20480u;
#pragma unroll
            for (int kk2 = 0; kk2 < 2; kk2++) {
                uint32_t a[2][4];
                ldsm4(a[0], Ab + aOff + kk2 * 32);
                ldsm4(a[1], Ab + aOff + 1280 + kk2 * 32);
#pragma unroll
                for (int ntp = 0; ntp < 4; ntp++) {
                    uint32_t b[4];
                    ldsm4(b, Bb + bOff + ntp * 1280 + kk2 * 32);
                    uint32_t b0[2] = {b[0], b[2]};
                    uint32_t b1[2] = {b[1], b[3]};
                    mma16816h(acc[0][2 * ntp],     a[0], b0);
                    mma16816h(acc[1][2 * ntp],     a[1], b0);
                    mma16816h(acc[0][2 * ntp + 1], a[0], b1);
                    mma16816h(acc[1][2 * ntp + 1], a[1], b1);
                }
            }
        }
        if (it < 15) storeStage(s ^ 1);
        __syncthreads();
    }

#pragma unroll
    for (int mt = 0; mt < 2; mt++) {
        int r0 = rowBase + wm + mt * 16 + gID;
#pragma unroll
        for (int nt = 0; nt < 8; nt++) {
            int cc = wn + nt * 8 + g4 * 2;
            if (r0 < M)
                *(float2*)(y1 + (size_t)r0 * 256 + cc) = make_float2(acc[mt][nt][0], acc[mt][nt][1]);
            if (r0 + 8 < M)
                *(float2*)(y1 + (size_t)(r0 + 8) * 256 + cc) = make_float2(acc[mt][nt][2], acc[mt][nt][3]);
        }
    }
}

// ===== GEMM2: y2[M,64] = h1[M,128] @ W2^T (fp16 2-pass, presplit h1) =======
__global__ __launch_bounds__(256) void gemm2_mma(float* __restrict__ y2, int M) {
    __shared__ __half sAh[128][40], sAl[128][40], sB[64][40];

    const int tid  = threadIdx.x;
    const int lane = tid & 31, wid = tid >> 5;
    const int wm = (wid & 3) * 32;
    const int wn = (wid >> 2) * 32;
    const int rowBase = blockIdx.x * 128;

    float acc[2][4][4];
#pragma unroll
    for (int i = 0; i < 2; i++)
#pragma unroll
        for (int j = 0; j < 4; j++)
#pragma unroll
            for (int q = 0; q < 4; q++) acc[i][j][q] = 0.f;

    const int g4 = lane & 3, gID = lane >> 2;
    const int sel = lane >> 3;
    const uint32_t rowInSel = (uint32_t)((sel & 1) * 8 + (lane & 7));
    const uint32_t colSel = (uint32_t)((sel >> 1) * 16);

    const uint32_t aHiB = su32(sAh), aLoB = su32(sAl), bB = su32(sB);
    const uint32_t aOff = (wm + rowInSel) * 80 + colSel;
    const uint32_t bOff = (wn + rowInSel) * 80 + colSel;

    for (int kt = 0; kt < 128; kt += 32) {
#pragma unroll
        for (int p = 0; p < 2; p++) {
            int j = tid + p * 256;
            int row = j >> 2, q = j & 3;
            int gr = rowBase + row;
            uint4 vh = make_uint4(0, 0, 0, 0), vl = vh;
            if (gr < M) {
                size_t gi = (size_t)gr * 128 + kt + q * 8;
                vh = *(const uint4*)(g_h1h + gi);
                vl = *(const uint4*)(g_h1l + gi);
            }
            *(uint4*)&sAh[row][q * 8] = vh;
            *(uint4*)&sAl[row][q * 8] = vl;
        }
        {
            int row = tid >> 2, q = tid & 3;
            if (row < 64)
                *(uint4*)&sB[row][q * 8] = *(const uint4*)(g_w2 + (size_t)row * 128 + kt + q * 8);
        }
        __syncthreads();

#pragma unroll
        for (int pass = 0; pass < 2; pass++) {
            uint32_t Ab = pass ? aLoB : aHiB;
#pragma unroll
            for (int kk2 = 0; kk2 < 2; kk2++) {
                uint32_t a[2][4];
                ldsm4(a[0], Ab + aOff + kk2 * 32);
                ldsm4(a[1], Ab + aOff + 1280 + kk2 * 32);
#pragma unroll
                for (int ntp = 0; ntp < 2; ntp++) {
                    uint32_t b[4];
                    ldsm4(b, bB + bOff + ntp * 1280 + kk2 * 32);
                    uint32_t b0[2] = {b[0], b[2]};
                    uint32_t b1[2] = {b[1], b[3]};
                    mma16816h(acc[0][2 * ntp],     a[0], b0);
                    mma16816h(acc[1][2 * ntp],     a[1], b0);
                    mma16816h(acc[0][2 * ntp + 1], a[0], b1);
                    mma16816h(acc[1][2 * ntp + 1], a[1], b1);
                }
            }
        }
        __syncthreads();
    }

#pragma unroll
    for (int mt = 0; mt < 2; mt++) {
        int r0 = rowBase + wm + mt * 16 + gID;
#pragma unroll
        for (int nt = 0; nt < 4; nt++) {
            int cc = wn + nt * 8 + g4 * 2;
            if (r0 < M)
                *(float2*)(y2 + (size_t)r0 * 64 + cc) = make_float2(acc[mt][nt][0], acc[mt][nt][1]);
            if (r0 + 8 < M)
                *(float2*)(y2 + (size_t)(r0 + 8) * 64 + cc) = make_float2(acc[mt][nt][2], acc[mt][nt][3]);
        }
    }
}

// ---------------- edge aggregation, layer 1 (128 feats, warp per edge) -----
__global__ void edge_agg1(const int* __restrict__ ei) {
    int gtid = blockIdx.x * blockDim.x + threadIdx.x;
    int e = gtid >> 5;
    int lane = gtid & 31;
    if (e >= N_EDGES) return;
    int src = ei[e];
    int dst = ei[N_EDGES + e];
    float4 v = *(const float4*)(g_y1 + (size_t)src * 256 + lane * 4);
    float* p = g_agg1 + (size_t)dst * 128 + lane * 4;
    asm volatile("red.global.add.v4.f32 [%0], {%1,%2,%3,%4};"
                 :: "l"(p), "f"(v.x), "f"(v.y), "f"(v.z), "f"(v.w) : "memory");
    if (lane == 0) atomicAdd(&g_cnt[dst], 1.0f);
}

// ------- layer-1 epilogue: h1 = relu(agg/cnt + b1l + y1r), split fp16 ------
__global__ void epi1(const float* __restrict__ b1l) {
    int idx = blockIdx.x * blockDim.x + threadIdx.x;   // N_NODES*32 float4 groups
    if (idx >= N_NODES * 32) return;
    int m = idx >> 5, q = idx & 31;
    float inv = 1.0f / fmaxf(g_cnt[m], 1.0f);
    float4 a = ((const float4*)g_agg1)[idx];
    float4 r = ((const float4*)g_y1)[(size_t)m * 64 + 32 + q];
    float4 b = ((const float4*)b1l)[q];
    float4 o;
    o.x = fmaxf(a.x * inv + b.x + r.x, 0.f);
    o.y = fmaxf(a.y * inv + b.y + r.y, 0.f);
    o.z = fmaxf(a.z * inv + b.z + r.z, 0.f);
    o.w = fmaxf(a.w * inv + b.w + r.w, 0.f);
    uint2 h, l;
    split4h(o, h, l);
    ((uint2*)g_h1h)[idx] = h;
    ((uint2*)g_h1l)[idx] = l;
}

// ---------------- edge aggregation, layer 2 (32 feats, 8 threads/edge) -----
__global__ void edge_agg2(const int* __restrict__ ei) {
    int gtid = blockIdx.x * blockDim.x + threadIdx.x;
    int e = gtid >> 3;
    int lane = gtid & 7;
    if (e >= N_EDGES) return;
    int src = ei[e];
    int dst = ei[N_EDGES + e];
    float4 v = *(const float4*)(g_y2 + (size_t)src * 64 + lane * 4);
    float* p = g_agg2 + (size_t)dst * 32 + lane * 4;
    asm volatile("red.global.add.v4.f32 [%0], {%1,%2,%3,%4};"
                 :: "l"(p), "f"(v.x), "f"(v.y), "f"(v.z), "f"(v.w) : "memory");
}

// ---------------- fused layer-2 epilogue + per-graph mean pool --------------
__global__ void pool_kernel(const int* __restrict__ batch, const float* __restrict__ b2l) {
    int f = threadIdx.x;           // 32
    int yid = threadIdx.y;         // 8
    int n0 = blockIdx.x * 512 + yid;
    float b = b2l[f];
    float acc = 0.f, cacc = 0.f;
    int cur = -1;
    for (int it = 0; it < 64; it++) {
        int n = n0 + it * 8;
        if (n < N_NODES) {
            int g = batch[n];
            if (g != cur) {
                if (cur >= 0) {
                    atomicAdd(&g_gsum[cur * 32 + f], acc);
                    if (f == 0) atomicAdd(&g_gcnt[cur], cacc);
                }
                cur = g; acc = 0.f; cacc = 0.f;
            }
            float inv = 1.0f / fmaxf(g_cnt[n], 1.0f);
            float v = g_agg2[(size_t)n * 32 + f] * inv + b + g_y2[(size_t)n * 64 + 32 + f];
            acc += fmaxf(v, 0.f);
            cacc += 1.f;
        }
    }
    if (cur >= 0) {
        atomicAdd(&g_gsum[cur * 32 + f], acc);
        if (f == 0) atomicAdd(&g_gcnt[cur], cacc);
    }
}

// ---------------- final tiny MLP (encoder head + decoder) ------------------
__global__ void mlp_kernel(const float* __restrict__ Wl1, const float* __restrict__ bl1,
                           const float* __restrict__ Wl2, const float* __restrict__ bl2,
                           const float* __restrict__ Wd1, const float* __restrict__ bd1,
                           const float* __restrict__ Wd2, const float* __restrict__ bd2,
                           const float* __restrict__ Wd3, const float* __restrict__ bd3,
                           float* __restrict__ out) {
    __shared__ float sWl1[1024], sWl2[512], sWd1[512], sWd2[1024], sWd3[1600];
    __shared__ float sbl1[32], sbl2[16], sbd1[32], sbd2[32], sbd3[50];
    int t = threadIdx.x;           // 64
    for (int i = t; i < 1024; i += 64) sWl1[i] = Wl1[i];
    for (int i = t; i < 512;  i += 64) sWl2[i] = Wl2[i];
    for (int i = t; i < 512;  i += 64) sWd1[i] = Wd1[i];
    for (int i = t; i < 1024; i += 64) sWd2[i] = Wd2[i];
    for (int i = t; i < 1600; i += 64) sWd3[i] = Wd3[i];
    if (t < 32) sbl1[t] = bl1[t];
    if (t < 16) sbl2[t] = bl2[t];
    if (t < 32) sbd1[t] = bd1[t];
    if (t < 32) sbd2[t] = bd2[t];
    for (int i = t; i < 50; i += 64) sbd3[i] = bd3[i];
    __syncthreads();
    if (t >= N_GRAPHS) return;

    float gv[32];
    float inv = 1.0f / fmaxf(g_gcnt[t], 1.0f);
#pragma unroll
    for (int i = 0; i < 32; i++) gv[i] = g_gsum[t * 32 + i] * inv;

    float a[32];
#pragma unroll
    for (int j = 0; j < 32; j++) {
        float s = sbl1[j];
#pragma unroll
        for (int i = 0; i < 32; i++) s = fmaf(gv[i], sWl1[i * 32 + j], s);
        a[j] = fmaxf(s, 0.f);
    }
    float enc[16];
#pragma unroll
    for (int j = 0; j < 16; j++) {
        float s = sbl2[j];
#pragma unroll
        for (int i = 0; i < 32; i++) s = fmaf(a[i], sWl2[i * 16 + j], s);
        enc[j] = s > 0.f ? s : 0.1f * s;
    }
#pragma unroll
    for (int j = 0; j < 16; j++) out[t * 16 + j] = enc[j];

    float z1[32];
#pragma unroll
    for (int j = 0; j < 32; j++) {
        float s = sbd1[j];
#pragma unroll
        for (int i = 0; i < 16; i++) s = fmaf(enc[i], sWd1[i * 32 + j], s);
        z1[j] = s > 0.f ? s : 0.1f * s;
    }
    float z2[32];
#pragma unroll
    for (int j = 0; j < 32; j++) {
        float s = sbd2[j];
#pragma unroll
        for (int i = 0; i < 32; i++) s = fmaf(z1[i], sWd2[i * 32 + j], s);
        z2[j] = s > 0.f ? s : 0.1f * s;
    }
#pragma unroll
    for (int j = 0; j < 50; j++) {
        float s = sbd3[j];
#pragma unroll
        for (int i = 0; i < 32; i++) s = fmaf(z2[i], sWd3[i * 50 + j], s);
        out[1024 + t * 50 + j] = s;
    }
}

// ---------------- launch ----------------------------------------------------
extern "C" void kernel_launch(void* const* d_in, const int* in_sizes, int n_in,
                              void* d_out, int out_size) {
    const float* x   = (const float*)d_in[0];
    const int*   ei  = (const int*)d_in[1];
    const int*   bat = (const int*)d_in[2];
    const float* W1l = (const float*)d_in[3];
    const float* b1l = (const float*)d_in[4];
    const float* W1r = (const float*)d_in[5];
    const float* W2l = (const float*)d_in[6];
    const float* b2l = (const float*)d_in[7];
    const float* W2r = (const float*)d_in[8];
    const float* Wl1 = (const float*)d_in[9];
    const float* bl1 = (const float*)d_in[10];
    const float* Wl2 = (const float*)d_in[11];
    const float* bl2 = (const float*)d_in[12];
    const float* Wd1 = (const float*)d_in[13];
    const float* bd1 = (const float*)d_in[14];
    const float* Wd2 = (const float*)d_in[15];
    const float* bd2 = (const float*)d_in[16];
    const float* Wd3 = (const float*)d_in[17];
    const float* bd3 = (const float*)d_in[18];
    float* out = (float*)d_out;

    float *p_y1, *p_y2;
    cudaGetSymbolAddress((void**)&p_y1, g_y1);
    cudaGetSymbolAddress((void**)&p_y2, g_y2);

    cudaFuncSetAttribute(gemm1_mma, cudaFuncAttributeMaxDynamicSharedMemorySize, SM_G1);

    zero_kernel<<<1184, 256>>>();
    convert_w<<<512, 256>>>(W1l, W1r);
    convert_w2<<<32, 256>>>(W2l, W2r);
    convert_x<<<12500, 256>>>((const float4*)x);

    // GEMM1 (tensor pipe, fp16 2-pass, LDG/STS double buffer)
    gemm1_mma<<<(N_NODES + 127) / 128, 512, SM_G1>>>(p_y1, N_NODES);

    edge_agg1<<<50000, 256>>>(ei);
    epi1<<<(N_NODES * 32 + 255) / 256, 256>>>(b1l);

    // GEMM2 (tensor pipe, fp16 2-pass)
    gemm2_mma<<<(N_NODES + 127) / 128, 256>>>(p_y2, N_NODES);

    edge_agg2<<<12500, 256>>>(ei);

    {
        dim3 blk(32, 8);
        pool_kernel<<<(N_NODES + 511) / 512, blk>>>(bat, b2l);
    }

    mlp_kernel<<<1, 64>>>(Wl1, bl1, Wl2, bl2, Wd1, bd1, Wd2, bd2, Wd3, bd3, out);
}

// round 8
// speedup vs baseline: 1.4644x; 1.3642x over previous
#include <cuda_runtime.h>
#include <cuda_fp16.h>
#include <cstdint>

#define N_NODES  50000
#define N_EDGES  400000
#define N_GRAPHS 64

// ============================ device scratch ===============================
__device__ __half g_w1[256 * 512];         // [W1l|W1r]^T fp16  [256 n][512 k]
__device__ __half g_w2[64 * 128];          // [W2l|W2r]^T fp16  [64 n][128 k]
__device__ __half g_h1[N_NODES * 128];     // h1 fp16
__device__ float g_y1[N_NODES * 256];
__device__ float g_agg1[N_NODES * 128];
__device__ float g_cnt[N_NODES];
__device__ float g_y2[N_NODES * 64];
__device__ float g_agg2[N_NODES * 32];
__device__ float g_gsum[N_GRAPHS * 32];
__device__ float g_gcnt[N_GRAPHS];

// ============================ zero accumulators ============================
__global__ void zero_kernel() {
    size_t i = (size_t)blockIdx.x * blockDim.x + threadIdx.x;
    size_t stride = (size_t)gridDim.x * blockDim.x;
    for (size_t k = i; k < (size_t)N_NODES * 128; k += stride) g_agg1[k] = 0.f;
    for (size_t k = i; k < (size_t)N_NODES * 32;  k += stride) g_agg2[k] = 0.f;
    for (size_t k = i; k < (size_t)N_NODES;       k += stride) g_cnt[k]  = 0.f;
    for (size_t k = i; k < (size_t)N_GRAPHS * 32; k += stride) g_gsum[k] = 0.f;
    for (size_t k = i; k < (size_t)N_GRAPHS;      k += stride) g_gcnt[k] = 0.f;
}

// ============================ helpers ======================================
__device__ __forceinline__ uint32_t su32(const void* p) {
    return (uint32_t)__cvta_generic_to_shared(p);
}
__device__ __forceinline__ uint32_t pack_h2(__half a, __half b) {
    __half2 t = __halves2half2(a, b);
    return *(uint32_t*)&t;
}
__device__ __forceinline__ uint2 cvt4h(float4 v) {
    return make_uint2(pack_h2(__float2half_rn(v.x), __float2half_rn(v.y)),
                      pack_h2(__float2half_rn(v.z), __float2half_rn(v.w)));
}
__device__ __forceinline__ void mma16816h(float* c, const uint32_t* a, const uint32_t* b) {
    asm volatile(
        "mma.sync.aligned.m16n8k16.row.col.f32.f16.f16.f32 "
        "{%0,%1,%2,%3}, {%4,%5,%6,%7}, {%8,%9}, {%0,%1,%2,%3};"
        : "+f"(c[0]), "+f"(c[1]), "+f"(c[2]), "+f"(c[3])
        : "r"(a[0]), "r"(a[1]), "r"(a[2]), "r"(a[3]), "r"(b[0]), "r"(b[1]));
}
__device__ __forceinline__ void ldsm4(uint32_t* r, uint32_t addr) {
    asm volatile("ldmatrix.sync.aligned.m8n8.x4.shared.b16 {%0,%1,%2,%3}, [%4];"
                 : "=r"(r[0]), "=r"(r[1]), "=r"(r[2]), "=r"(r[3]) : "r"(addr));
}

// ==================== weight conversions (fp16) =============================
__global__ void convert_w(const float* __restrict__ Wl, const float* __restrict__ Wr) {
    int idx = blockIdx.x * blockDim.x + threadIdx.x;
    if (idx >= 256 * 512) return;
    int n = idx >> 9, k = idx & 511;
    float v = (n < 128) ? Wl[k * 128 + n] : Wr[k * 128 + (n - 128)];
    g_w1[idx] = __float2half_rn(v);
}
__global__ void convert_w2(const float* __restrict__ Wl, const float* __restrict__ Wr) {
    int idx = blockIdx.x * blockDim.x + threadIdx.x;
    if (idx >= 64 * 128) return;
    int n = idx >> 7, k = idx & 127;
    float v = (n < 32) ? Wl[k * 32 + n] : Wr[k * 32 + (n - 32)];
    g_w2[idx] = __float2half_rn(v);
}

// ===== GEMM1: y1[M,256] = x[M,512] @ W1^T  (single fp16, fused convert) ====
// 512 threads, CTA tile 128(M) x 256(N), BK=32, LDG->reg(cvt)->STS 2-stage.
// stage: A 128*80 + B 256*80 = 30720 B; 2 stages = 61440 B dynamic smem.
#define G1_STAGE 30720
#define SM_G1 (2 * G1_STAGE)

__global__ __launch_bounds__(512) void gemm1_mma(const float* __restrict__ x,
                                                 float* __restrict__ y1, int M) {
    extern __shared__ char smem[];
    const uint32_t sb = su32(smem);
    const int tid  = threadIdx.x;
    const int lane = tid & 31, wid = tid >> 5;
    const int wm = (wid & 3) * 32;
    const int wn = (wid >> 2) * 64;
    const int rowBase = blockIdx.x * 128;

    float acc[2][8][4];
#pragma unroll
    for (int i = 0; i < 2; i++)
#pragma unroll
        for (int j = 0; j < 8; j++)
#pragma unroll
            for (int q = 0; q < 4; q++) acc[i][j][q] = 0.f;

    const int g4 = lane & 3, gID = lane >> 2;
    const int sel = lane >> 3;
    const uint32_t rowInSel = (uint32_t)((sel & 1) * 8 + (lane & 7));
    const uint32_t colSel = (uint32_t)((sel >> 1) * 16);
    const uint32_t aOff = (wm + rowInSel) * 80 + colSel;
    const uint32_t bOff = (wn + rowInSel) * 80 + colSel;

    // A: 128 rows x 32 k fp32 -> per thread one 16B-fp16 chunk (8 floats)
    const int arow = tid >> 2, aq = tid & 3;
    const int gra = rowBase + arow;
    const bool av = (gra < M);
    const size_t agi = (size_t)(av ? gra : 0) * 512 + aq * 8;
    const uint32_t sAo = arow * 80 + aq * 16;
    // B: 256 rows x 32 halves = 1024 16B-chunks -> 2 per thread
    const size_t bgi0 = (size_t)(tid >> 2) * 512 + (tid & 3) * 8;
    const size_t bgi1 = (size_t)((tid >> 2) + 128) * 512 + (tid & 3) * 8;
    const uint32_t sBo0 = 10240 + (tid >> 2) * 80 + (tid & 3) * 16;
    const uint32_t sBo1 = 10240 + ((tid >> 2) + 128) * 80 + (tid & 3) * 16;

    float4 ra0, ra1;
    uint4 rb0, rb1;
    const float4 zf4 = make_float4(0.f, 0.f, 0.f, 0.f);

    auto loadRegs = [&](int kt) {
        ra0 = av ? *(const float4*)(x + agi + kt)     : zf4;
        ra1 = av ? *(const float4*)(x + agi + kt + 4) : zf4;
        rb0 = *(const uint4*)(g_w1 + bgi0 + kt);
        rb1 = *(const uint4*)(g_w1 + bgi1 + kt);
    };
    auto storeStage = [&](int s) {
        char* st = smem + s * G1_STAGE;
        uint2 h0 = cvt4h(ra0), h1 = cvt4h(ra1);
        *(uint4*)(st + sAo)  = make_uint4(h0.x, h0.y, h1.x, h1.y);
        *(uint4*)(st + sBo0) = rb0;
        *(uint4*)(st + sBo1) = rb1;
    };

    loadRegs(0);
    storeStage(0);
    __syncthreads();

    for (int it = 0; it < 16; it++) {
        const int s = it & 1;
        if (it < 15) loadRegs((it + 1) * 32);

        const uint32_t Ab = sb + s * G1_STAGE;
        const uint32_t Bb = Ab + 10240u;
#pragma unroll
        for (int kk2 = 0; kk2 < 2; kk2++) {
            uint32_t a[2][4];
            ldsm4(a[0], Ab + aOff + kk2 * 32);
            ldsm4(a[1], Ab + aOff + 1280 + kk2 * 32);
#pragma unroll
            for (int ntp = 0; ntp < 4; ntp++) {
                uint32_t b[4];
                ldsm4(b, Bb + bOff + ntp * 1280 + kk2 * 32);
                uint32_t b0[2] = {b[0], b[2]};
                uint32_t b1[2] = {b[1], b[3]};
                mma16816h(acc[0][2 * ntp],     a[0], b0);
                mma16816h(acc[1][2 * ntp],     a[1], b0);
                mma16816h(acc[0][2 * ntp + 1], a[0], b1);
                mma16816h(acc[1][2 * ntp + 1], a[1], b1);
            }
        }
        if (it < 15) storeStage(s ^ 1);
        __syncthreads();
    }

#pragma unroll
    for (int mt = 0; mt < 2; mt++) {
        int r0 = rowBase + wm + mt * 16 + gID;
#pragma unroll
        for (int nt = 0; nt < 8; nt++) {
            int cc = wn + nt * 8 + g4 * 2;
            if (r0 < M)
                *(float2*)(y1 + (size_t)r0 * 256 + cc) = make_float2(acc[mt][nt][0], acc[mt][nt][1]);
            if (r0 + 8 < M)
                *(float2*)(y1 + (size_t)(r0 + 8) * 256 + cc) = make_float2(acc[mt][nt][2], acc[mt][nt][3]);
        }
    }
}

// ===== GEMM2: y2[M,64] = h1[M,128] @ W2^T (single fp16) =====================
__global__ __launch_bounds__(256) void gemm2_mma(float* __restrict__ y2, int M) {
    __shared__ __half sA[128][40], sB[64][40];

    const int tid  = threadIdx.x;
    const int lane = tid & 31, wid = tid >> 5;
    const int wm = (wid & 3) * 32;
    const int wn = (wid >> 2) * 32;
    const int rowBase = blockIdx.x * 128;

    float acc[2][4][4];
#pragma unroll
    for (int i = 0; i < 2; i++)
#pragma unroll
        for (int j = 0; j < 4; j++)
#pragma unroll
            for (int q = 0; q < 4; q++) acc[i][j][q] = 0.f;

    const int g4 = lane & 3, gID = lane >> 2;
    const int sel = lane >> 3;
    const uint32_t rowInSel = (uint32_t)((sel & 1) * 8 + (lane & 7));
    const uint32_t colSel = (uint32_t)((sel >> 1) * 16);

    const uint32_t aB = su32(sA), bB = su32(sB);
    const uint32_t aOff = (wm + rowInSel) * 80 + colSel;
    const uint32_t bOff = (wn + rowInSel) * 80 + colSel;

    for (int kt = 0; kt < 128; kt += 32) {
        // A: 128 rows x 32 halves = 512 chunks -> 2/thread
#pragma unroll
        for (int p = 0; p < 2; p++) {
            int j = tid + p * 256;
            int row = j >> 2, q = j & 3;
            int gr = rowBase + row;
            uint4 v = make_uint4(0, 0, 0, 0);
            if (gr < M) v = *(const uint4*)(g_h1 + (size_t)gr * 128 + kt + q * 8);
            *(uint4*)&sA[row][q * 8] = v;
        }
        // B: 64 rows x 32 halves = 256 chunks -> 1/thread
        {
            int row = tid >> 2, q = tid & 3;
            if (row < 64)
                *(uint4*)&sB[row][q * 8] = *(const uint4*)(g_w2 + (size_t)row * 128 + kt + q * 8);
        }
        __syncthreads();

#pragma unroll
        for (int kk2 = 0; kk2 < 2; kk2++) {
            uint32_t a[2][4];
            ldsm4(a[0], aB + aOff + kk2 * 32);
            ldsm4(a[1], aB + aOff + 1280 + kk2 * 32);
#pragma unroll
            for (int ntp = 0; ntp < 2; ntp++) {
                uint32_t b[4];
                ldsm4(b, bB + bOff + ntp * 1280 + kk2 * 32);
                uint32_t b0[2] = {b[0], b[2]};
                uint32_t b1[2] = {b[1], b[3]};
                mma16816h(acc[0][2 * ntp],     a[0], b0);
                mma16816h(acc[1][2 * ntp],     a[1], b0);
                mma16816h(acc[0][2 * ntp + 1], a[0], b1);
                mma16816h(acc[1][2 * ntp + 1], a[1], b1);
            }
        }
        __syncthreads();
    }

#pragma unroll
    for (int mt = 0; mt < 2; mt++) {
        int r0 = rowBase + wm + mt * 16 + gID;
#pragma unroll
        for (int nt = 0; nt < 4; nt++) {
            int cc = wn + nt * 8 + g4 * 2;
            if (r0 < M)
                *(float2*)(y2 + (size_t)r0 * 64 + cc) = make_float2(acc[mt][nt][0], acc[mt][nt][1]);
            if (r0 + 8 < M)
                *(float2*)(y2 + (size_t)(r0 + 8) * 64 + cc) = make_float2(acc[mt][nt][2], acc[mt][nt][3]);
        }
    }
}

// ---------------- edge aggregation, layer 1 (128 feats, warp per edge) -----
__global__ void edge_agg1(const int* __restrict__ ei) {
    int gtid = blockIdx.x * blockDim.x + threadIdx.x;
    int e = gtid >> 5;
    int lane = gtid & 31;
    if (e >= N_EDGES) return;
    int src = ei[e];
    int dst = ei[N_EDGES + e];
    float4 v = *(const float4*)(g_y1 + (size_t)src * 256 + lane * 4);
    float* p = g_agg1 + (size_t)dst * 128 + lane * 4;
    asm volatile("red.global.add.v4.f32 [%0], {%1,%2,%3,%4};"
                 :: "l"(p), "f"(v.x), "f"(v.y), "f"(v.z), "f"(v.w) : "memory");
    if (lane == 0) atomicAdd(&g_cnt[dst], 1.0f);
}

// ------- layer-1 epilogue: h1 = relu(agg/cnt + b1l + y1r) -> fp16 ----------
__global__ void epi1(const float* __restrict__ b1l) {
    int idx = blockIdx.x * blockDim.x + threadIdx.x;   // N_NODES*32 float4 groups
    if (idx >= N_NODES * 32) return;
    int m = idx >> 5, q = idx & 31;
    float inv = 1.0f / fmaxf(g_cnt[m], 1.0f);
    float4 a = ((const float4*)g_agg1)[idx];
    float4 r = ((const float4*)g_y1)[(size_t)m * 64 + 32 + q];
    float4 b = ((const float4*)b1l)[q];
    float4 o;
    o.x = fmaxf(a.x * inv + b.x + r.x, 0.f);
    o.y = fmaxf(a.y * inv + b.y + r.y, 0.f);
    o.z = fmaxf(a.z * inv + b.z + r.z, 0.f);
    o.w = fmaxf(a.w * inv + b.w + r.w, 0.f);
    ((uint2*)g_h1)[idx] = cvt4h(o);
}

// ---------------- edge aggregation, layer 2 (32 feats, 8 threads/edge) -----
__global__ void edge_agg2(const int* __restrict__ ei) {
    int gtid = blockIdx.x * blockDim.x + threadIdx.x;
    int e = gtid >> 3;
    int lane = gtid & 7;
    if (e >= N_EDGES) return;
    int src = ei[e];
    int dst = ei[N_EDGES + e];
    float4 v = *(const float4*)(g_y2 + (size_t)src * 64 + lane * 4);
    float* p = g_agg2 + (size_t)dst * 32 + lane * 4;
    asm volatile("red.global.add.v4.f32 [%0], {%1,%2,%3,%4};"
                 :: "l"(p), "f"(v.x), "f"(v.y), "f"(v.z), "f"(v.w) : "memory");
}

// ---------------- fused layer-2 epilogue + per-graph mean pool --------------
__global__ void pool_kernel(const int* __restrict__ batch, const float* __restrict__ b2l) {
    int f = threadIdx.x;           // 32
    int yid = threadIdx.y;         // 8
    int n0 = blockIdx.x * 512 + yid;
    float b = b2l[f];
    float acc = 0.f, cacc = 0.f;
    int cur = -1;
    for (int it = 0; it < 64; it++) {
        int n = n0 + it * 8;
        if (n < N_NODES) {
            int g = batch[n];
            if (g != cur) {
                if (cur >= 0) {
                    atomicAdd(&g_gsum[cur * 32 + f], acc);
                    if (f == 0) atomicAdd(&g_gcnt[cur], cacc);
                }
                cur = g; acc = 0.f; cacc = 0.f;
            }
            float inv = 1.0f / fmaxf(g_cnt[n], 1.0f);
            float v = g_agg2[(size_t)n * 32 + f] * inv + b + g_y2[(size_t)n * 64 + 32 + f];
            acc += fmaxf(v, 0.f);
            cacc += 1.f;
        }
    }
    if (cur >= 0) {
        atomicAdd(&g_gsum[cur * 32 + f], acc);
        if (f == 0) atomicAdd(&g_gcnt[cur], cacc);
    }
}

// ---------------- final tiny MLP (encoder head + decoder) ------------------
__global__ void mlp_kernel(const float* __restrict__ Wl1, const float* __restrict__ bl1,
                           const float* __restrict__ Wl2, const float* __restrict__ bl2,
                           const float* __restrict__ Wd1, const float* __restrict__ bd1,
                           const float* __restrict__ Wd2, const float* __restrict__ bd2,
                           const float* __restrict__ Wd3, const float* __restrict__ bd3,
                           float* __restrict__ out) {
    __shared__ float sWl1[1024], sWl2[512], sWd1[512], sWd2[1024], sWd3[1600];
    __shared__ float sbl1[32], sbl2[16], sbd1[32], sbd2[32], sbd3[50];
    int t = threadIdx.x;           // 64
    for (int i = t; i < 1024; i += 64) sWl1[i] = Wl1[i];
    for (int i = t; i < 512;  i += 64) sWl2[i] = Wl2[i];
    for (int i = t; i < 512;  i += 64) sWd1[i] = Wd1[i];
    for (int i = t; i < 1024; i += 64) sWd2[i] = Wd2[i];
    for (int i = t; i < 1600; i += 64) sWd3[i] = Wd3[i];
    if (t < 32) sbl1[t] = bl1[t];
    if (t < 16) sbl2[t] = bl2[t];
    if (t < 32) sbd1[t] = bd1[t];
    if (t < 32) sbd2[t] = bd2[t];
    for (int i = t; i < 50; i += 64) sbd3[i] = bd3[i];
    __syncthreads();
    if (t >= N_GRAPHS) return;

    float gv[32];
    float inv = 1.0f / fmaxf(g_gcnt[t], 1.0f);
#pragma unroll
    for (int i = 0; i < 32; i++) gv[i] = g_gsum[t * 32 + i] * inv;

    float a[32];
#pragma unroll
    for (int j = 0; j < 32; j++) {
        float s = sbl1[j];
#pragma unroll
        for (int i = 0; i < 32; i++) s = fmaf(gv[i], sWl1[i * 32 + j], s);
        a[j] = fmaxf(s, 0.f);
    }
    float enc[16];
#pragma unroll
    for (int j = 0; j < 16; j++) {
        float s = sbl2[j];
#pragma unroll
        for (int i = 0; i < 32; i++) s = fmaf(a[i], sWl2[i * 16 + j], s);
        enc[j] = s > 0.f ? s : 0.1f * s;
    }
#pragma unroll
    for (int j = 0; j < 16; j++) out[t * 16 + j] = enc[j];

    float z1[32];
#pragma unroll
    for (int j = 0; j < 32; j++) {
        float s = sbd1[j];
#pragma unroll
        for (int i = 0; i < 16; i++) s = fmaf(enc[i], sWd1[i * 32 + j], s);
        z1[j] = s > 0.f ? s : 0.1f * s;
    }
    float z2[32];
#pragma unroll
    for (int j = 0; j < 32; j++) {
        float s = sbd2[j];
#pragma unroll
        for (int i = 0; i < 32; i++) s = fmaf(z1[i], sWd2[i * 32 + j], s);
        z2[j] = s > 0.f ? s : 0.1f * s;
    }
#pragma unroll
    for (int j = 0; j < 50; j++) {
        float s = sbd3[j];
#pragma unroll
        for (int i = 0; i < 32; i++) s = fmaf(z2[i], sWd3[i * 50 + j], s);
        out[1024 + t * 50 + j] = s;
    }
}

// ---------------- launch ----------------------------------------------------
extern "C" void kernel_launch(void* const* d_in, const int* in_sizes, int n_in,
                              void* d_out, int out_size) {
    const float* x   = (const float*)d_in[0];
    const int*   ei  = (const int*)d_in[1];
    const int*   bat = (const int*)d_in[2];
    const float* W1l = (const float*)d_in[3];
    const float* b1l = (const float*)d_in[4];
    const float* W1r = (const float*)d_in[5];
    const float* W2l = (const float*)d_in[6];
    const float* b2l = (const float*)d_in[7];
    const float* W2r = (const float*)d_in[8];
    const float* Wl1 = (const float*)d_in[9];
    const float* bl1 = (const float*)d_in[10];
    const float* Wl2 = (const float*)d_in[11];
    const float* bl2 = (const float*)d_in[12];
    const float* Wd1 = (const float*)d_in[13];
    const float* bd1 = (const float*)d_in[14];
    const float* Wd2 = (const float*)d_in[15];
    const float* bd2 = (const float*)d_in[16];
    const float* Wd3 = (const float*)d_in[17];
    const float* bd3 = (const float*)d_in[18];
    float* out = (float*)d_out;

    float *p_y1, *p_y2;
    cudaGetSymbolAddress((void**)&p_y1, g_y1);
    cudaGetSymbolAddress((void**)&p_y2, g_y2);

    cudaFuncSetAttribute(gemm1_mma, cudaFuncAttributeMaxDynamicSharedMemorySize, SM_G1);

    zero_kernel<<<1184, 256>>>();
    convert_w<<<512, 256>>>(W1l, W1r);
    convert_w2<<<32, 256>>>(W2l, W2r);

    // GEMM1 (tensor pipe, single fp16, fused fp32->fp16 convert)
    gemm1_mma<<<(N_NODES + 127) / 128, 512, SM_G1>>>(x, p_y1, N_NODES);

    edge_agg1<<<50000, 256>>>(ei);
    epi1<<<(N_NODES * 32 + 255) / 256, 256>>>(b1l);

    // GEMM2 (tensor pipe, single fp16)
    gemm2_mma<<<(N_NODES + 127) / 128, 256>>>(p_y2, N_NODES);

    edge_agg2<<<12500, 256>>>(ei);

    {
        dim3 blk(32, 8);
        pool_kernel<<<(N_NODES + 511) / 512, blk>>>(bat, b2l);
    }

    mlp_kernel<<<1, 64>>>(Wl1, bl1, Wl2, bl2, Wd1, bd1, Wd2, bd2, Wd3, bd3, out);
}